// round 8
// baseline (speedup 1.0000x reference)
#include <cuda_runtime.h>
#include <cuda_bf16.h>
#include <stdint.h>
#include <math.h>

#define Bm 64
#define Tm 256
#define DIN 512
#define Hm 1024
#define G4 4096
#define C_OUT 1000
#define BT (Bm*Tm)
#define NCTA 128

// ---------------- device scratch (packed bf16 pairs: 2 elems / uint32) ------
__device__ uint32_t g_xh[BT*DIN/2],  g_xl[BT*DIN/2];
__device__ uint32_t g_sh[(size_t)BT*Hm/2], g_sl[(size_t)BT*Hm/2];
__device__ uint32_t g_wih0h[G4*DIN/2], g_wih0l[G4*DIN/2];
__device__ uint32_t g_whh0h[G4*Hm/2],  g_whh0l[G4*Hm/2];
__device__ uint32_t g_wih1h[G4*Hm/2],  g_wih1l[G4*Hm/2];
__device__ uint32_t g_whh1h[G4*Hm/2],  g_whh1l[G4*Hm/2];
__device__ uint32_t g_fwh[C_OUT*Hm/2], g_fwl[C_OUT*Hm/2];
__device__ uint32_t g_h0h[2*Bm*Hm/2], g_h0l[2*Bm*Hm/2];
__device__ uint32_t g_h1h[2*Bm*Hm/2], g_h1l[2*Bm*Hm/2];
__device__ float    g_xg[(size_t)BT*G4];
__device__ unsigned g_flags[32];   // 2 layers x 16 producer-group counters

// ---------------- helpers ----------------------------------------------------
__device__ __forceinline__ float sigf(float x) { return 1.0f / (1.0f + __expf(-x)); }
__device__ __forceinline__ float tanhx(float x) {
    float a = fabsf(x);
    float e = __expf(-2.0f * a);
    float r = (1.0f - e) / (1.0f + e);
    return x < 0.0f ? -r : r;
}
__device__ __forceinline__ uint32_t smemu32(const void* p) {
    return (uint32_t)__cvta_generic_to_shared(p);
}
__device__ __forceinline__ void ldsm4(uint32_t& r0, uint32_t& r1, uint32_t& r2, uint32_t& r3,
                                      uint32_t addr) {
    asm volatile("ldmatrix.sync.aligned.m8n8.x4.shared.b16 {%0,%1,%2,%3}, [%4];"
                 : "=r"(r0), "=r"(r1), "=r"(r2), "=r"(r3) : "r"(addr));
}
__device__ __forceinline__ void mma_bf16(float* c,
    uint32_t a0, uint32_t a1, uint32_t a2, uint32_t a3, uint32_t b0, uint32_t b1)
{
    asm volatile(
        "mma.sync.aligned.m16n8k16.row.col.f32.bf16.bf16.f32 "
        "{%0,%1,%2,%3}, {%4,%5,%6,%7}, {%8,%9}, {%0,%1,%2,%3};\n"
        : "+f"(c[0]), "+f"(c[1]), "+f"(c[2]), "+f"(c[3])
        : "r"(a0), "r"(a1), "r"(a2), "r"(a3), "r"(b0), "r"(b1));
}
__device__ __forceinline__ void cpasync16(uint32_t smem_dst, const void* gsrc) {
    asm volatile("cp.async.cg.shared.global [%0], [%1], 16;" :: "r"(smem_dst), "l"(gsrc));
}
__device__ __forceinline__ unsigned ld_acq(const unsigned* p) {
    unsigned v;
    asm volatile("ld.acquire.gpu.global.u32 %0, [%1];" : "=r"(v) : "l"(p));
    return v;
}

// ---------------- fused split: all 6 fp32 tensors -> bf16 hi/lo -------------
#define S0 (BT*DIN/2)
#define S1 (G4*DIN/2)
#define S2 (G4*Hm/2)
#define STOT (S0 + S1 + 3*S2 + C_OUT*Hm/2)

__global__ void splitall(
    const float* __restrict__ x,  const float* __restrict__ wi0,
    const float* __restrict__ wh0, const float* __restrict__ wi1,
    const float* __restrict__ wh1, const float* __restrict__ fw,
    uint32_t* xh, uint32_t* xl, uint32_t* wi0h, uint32_t* wi0l,
    uint32_t* wh0h, uint32_t* wh0l, uint32_t* wi1h, uint32_t* wi1l,
    uint32_t* wh1h, uint32_t* wh1l, uint32_t* fwh, uint32_t* fwl)
{
    int i = blockIdx.x * blockDim.x + threadIdx.x;
    if (i >= STOT) return;
    const float* s; uint32_t *H, *L; int off;
    if      (i < S0)                   { s = x;   H = xh;   L = xl;   off = i; }
    else if (i < S0 + S1)              { s = wi0; H = wi0h; L = wi0l; off = i - S0; }
    else if (i < S0 + S1 + S2)         { s = wh0; H = wh0h; L = wh0l; off = i - S0 - S1; }
    else if (i < S0 + S1 + 2*S2)       { s = wi1; H = wi1h; L = wi1l; off = i - S0 - S1 - S2; }
    else if (i < S0 + S1 + 3*S2)       { s = wh1; H = wh1h; L = wh1l; off = i - S0 - S1 - 2*S2; }
    else                               { s = fw;  H = fwh;  L = fwl;  off = i - S0 - S1 - 3*S2; }
    float2 v = ((const float2*)s)[off];
    __nv_bfloat16 h0 = __float2bfloat16_rn(v.x);
    __nv_bfloat16 h1 = __float2bfloat16_rn(v.y);
    __nv_bfloat16 l0 = __float2bfloat16_rn(v.x - __bfloat162float(h0));
    __nv_bfloat16 l1 = __float2bfloat16_rn(v.y - __bfloat162float(h1));
    H[off] = (uint32_t)__bfloat16_as_ushort(h0) | ((uint32_t)__bfloat16_as_ushort(h1) << 16);
    L[off] = (uint32_t)__bfloat16_as_ushort(l0) | ((uint32_t)__bfloat16_as_ushort(l1) << 16);
}

__global__ void zeroh(uint32_t* a, uint32_t* b, uint32_t* c, uint32_t* d, int n,
                      unsigned* flags) {
    int i = blockIdx.x * blockDim.x + threadIdx.x;
    if (i < n) { a[i] = 0; b[i] = 0; c[i] = 0; d[i] = 0; }
    if (i < 32) flags[i] = 0;
}

// ============================================================================
// gemmT: unchanged (bf16x3, smem-staged + ldmatrix).
// ============================================================================
__global__ __launch_bounds__(256, 1) void gemmT(
    const uint32_t* __restrict__ Ah, const uint32_t* __restrict__ Al,
    const uint32_t* __restrict__ Bh, const uint32_t* __restrict__ Bl,
    const float* __restrict__ b1, const float* __restrict__ b2,
    float* __restrict__ C, int M, int N, int K)
{
    __shared__ uint32_t AhS[128 * 20], AlS[128 * 20], BhS[128 * 20], BlS[128 * 20];

    const int K2 = K >> 1;
    const int tid = threadIdx.x;
    const int wid = tid >> 5, lane = tid & 31;
    const int g = lane >> 2, tig = lane & 3;
    const int wm = wid >> 2, wn = wid & 3;
    const int bm = blockIdx.y * 128, bn = blockIdx.x * 128;

    const int lr0 = tid >> 2, lc = tid & 3;
    const int ar0 = min(bm + lr0, M - 1) * K2;
    const int ar1 = min(bm + lr0 + 64, M - 1) * K2;
    const int br0 = ((bn + lr0      < N) ? bn + lr0      : 0) * K2;
    const int br1 = ((bn + lr0 + 64 < N) ? bn + lr0 + 64 : 0) * K2;

    uint4 pA0, pA1, pAl0, pAl1, pB0, pB1, pBl0, pBl1;
    auto loadG = [&](int kc) {
        const int go = kc * 16 + lc * 4;
        pA0  = *(const uint4*)&Ah[ar0 + go];  pA1  = *(const uint4*)&Ah[ar1 + go];
        pAl0 = *(const uint4*)&Al[ar0 + go];  pAl1 = *(const uint4*)&Al[ar1 + go];
        pB0  = *(const uint4*)&Bh[br0 + go];  pB1  = *(const uint4*)&Bh[br1 + go];
        pBl0 = *(const uint4*)&Bl[br0 + go];  pBl1 = *(const uint4*)&Bl[br1 + go];
    };

    float acc[4][4][4];
#pragma unroll
    for (int im = 0; im < 4; im++)
#pragma unroll
        for (int p = 0; p < 4; p++)
#pragma unroll
            for (int q = 0; q < 4; q++) acc[im][p][q] = 0.0f;

    const int lrow = lane & 15, lhalf = lane >> 4;
    const uint32_t aBase = smemu32(AhS), alBase = smemu32(AlS);
    const uint32_t bBase = smemu32(BhS), blBase = smemu32(BlS);

    const int nk = K >> 5;
    loadG(0);
    for (int kc = 0; kc < nk; kc++) {
        __syncthreads();
        {
            const int s0 = lr0 * 20 + lc * 4, s1 = (lr0 + 64) * 20 + lc * 4;
            *(uint4*)&AhS[s0] = pA0;  *(uint4*)&AhS[s1] = pA1;
            *(uint4*)&AlS[s0] = pAl0; *(uint4*)&AlS[s1] = pAl1;
            *(uint4*)&BhS[s0] = pB0;  *(uint4*)&BhS[s1] = pB1;
            *(uint4*)&BlS[s0] = pBl0; *(uint4*)&BlS[s1] = pBl1;
        }
        __syncthreads();
        if (kc + 1 < nk) loadG(kc + 1);

#pragma unroll
        for (int k16 = 0; k16 < 2; k16++) {
            const uint32_t coff = (uint32_t)((k16 * 2 + lhalf) * 16);
            uint32_t bh[2][4], bl[2][4];
#pragma unroll
            for (int p16 = 0; p16 < 2; p16++) {
                const uint32_t bro = (uint32_t)((wn * 32 + p16 * 16 + lrow) * 80);
                ldsm4(bh[p16][0], bh[p16][1], bh[p16][2], bh[p16][3], bBase + bro + coff);
                ldsm4(bl[p16][0], bl[p16][1], bl[p16][2], bl[p16][3], blBase + bro + coff);
            }
#pragma unroll
            for (int im = 0; im < 4; im++) {
                const uint32_t aro = (uint32_t)((wm * 64 + im * 16 + lrow) * 80);
                uint32_t ah0, ah1, ah2, ah3, al0, al1, al2, al3;
                ldsm4(ah0, ah1, ah2, ah3, aBase + aro + coff);
                ldsm4(al0, al1, al2, al3, alBase + aro + coff);
#pragma unroll
                for (int p16 = 0; p16 < 2; p16++) {
                    mma_bf16(acc[im][p16 * 2 + 0], ah0, ah1, ah2, ah3, bh[p16][0], bh[p16][2]);
                    mma_bf16(acc[im][p16 * 2 + 1], ah0, ah1, ah2, ah3, bh[p16][1], bh[p16][3]);
                    mma_bf16(acc[im][p16 * 2 + 0], ah0, ah1, ah2, ah3, bl[p16][0], bl[p16][2]);
                    mma_bf16(acc[im][p16 * 2 + 1], ah0, ah1, ah2, ah3, bl[p16][1], bl[p16][3]);
                    mma_bf16(acc[im][p16 * 2 + 0], al0, al1, al2, al3, bh[p16][0], bh[p16][2]);
                    mma_bf16(acc[im][p16 * 2 + 1], al0, al1, al2, al3, bh[p16][1], bh[p16][3]);
                }
            }
        }
    }

#pragma unroll
    for (int im = 0; im < 4; im++) {
        const int r0 = bm + wm * 64 + im * 16 + g;
        const int r1 = r0 + 8;
#pragma unroll
        for (int p = 0; p < 4; p++) {
            const int c = bn + wn * 32 + p * 8 + 2 * tig;
            if (c < N) {
                const float bb0 = b1[c]     + (b2 ? b2[c]     : 0.0f);
                const float bb1 = b1[c + 1] + (b2 ? b2[c + 1] : 0.0f);
                if (r0 < M)
                    *(float2*)&C[(size_t)r0 * N + c] =
                        make_float2(acc[im][p][0] + bb0, acc[im][p][1] + bb1);
                if (r1 < M)
                    *(float2*)&C[(size_t)r1 * N + c] =
                        make_float2(acc[im][p][2] + bb0, acc[im][p][3] + bb1);
            }
        }
    }
}

// ============================================================================
// lstm_persist: dataflow-synchronized persistent LSTM layer.
// 128 CTAs x 512 thr (2 K-half warpgroups x 4m x 2n warps).
// NO grid barrier: 16 producer-group counters (8 CTAs each). A CTA publishes
// its 8 hidden units' h with one atomicAdd; consumers wait per-chunk with an
// acquire-load spin only on the 8 producers of that chunk. Skew pipelines
// instead of accumulating.
// ============================================================================
#define SW_WL   16512
#define SW_A    33024
#define A_ARR   2304        // 64 rows * 36 uints
#define SW_GS   51456
#define SMEM_UINTS 55808    // 223,232 bytes

__global__ __launch_bounds__(512, 1) void lstm_persist(
    const uint32_t* __restrict__ Wg_h, const uint32_t* __restrict__ Wg_l,
    uint32_t* __restrict__ hbH, uint32_t* __restrict__ hbL,
    const float* __restrict__ xg,
    uint32_t* __restrict__ seqH, uint32_t* __restrict__ seqL,
    unsigned* __restrict__ flags)     // 16 counters for this layer
{
    extern __shared__ uint32_t sm[];
    uint32_t* WhS = sm;
    uint32_t* WlS = sm + SW_WL;
    float*    gs0 = (float*)(sm + SW_GS);
    float*    gs1 = (float*)(sm + SW_GS + 2176);

    const int tid = threadIdx.x;
    const int wid = tid >> 5, lane = tid & 31;
    const int g = lane >> 2, tig = lane & 3;
    const int wg = wid >> 3;
    const int w8 = wid & 7;
    const int wm = w8 >> 1, wn = w8 & 1;
    const int h0 = blockIdx.x * 8;
    const int K2 = Hm / 2;
    const int HBUF = Bm * Hm / 2;
    const int mygrp = blockIdx.x >> 3;          // producer group of this CTA

    // ---- prologue: W slice -> smem (32 rows x 512 uints, hi+lo) ----
#pragma unroll
    for (int i = 0; i < 8; i++) {
        const int u = tid + 512 * i;
        const int r = u >> 7, c = (u & 127) * 4;
        const int grow = ((r >> 3) * Hm + h0 + (r & 7)) * K2;
        *(uint4*)&WhS[r * 516 + c] = *(const uint4*)&Wg_h[grow + c];
        *(uint4*)&WlS[r * 516 + c] = *(const uint4*)&Wg_l[grow + c];
    }

    const int lrow = lane & 15, lhalf = lane >> 4;
    const uint32_t smB = smemu32(sm);
    uint32_t aHiB[2], aLoB[2];
#pragma unroll
    for (int b = 0; b < 2; b++) {
        aHiB[b] = smB + (uint32_t)((SW_A + ((wg * 2 + b) * 2 + 0) * A_ARR) * 4)
                      + (uint32_t)((wm * 16 + lrow) * 144);
        aLoB[b] = smB + (uint32_t)((SW_A + ((wg * 2 + b) * 2 + 1) * A_ARR) * 4)
                      + (uint32_t)((wm * 16 + lrow) * 144);
    }
    const uint32_t wBase  = smB + (uint32_t)((wn * 16 + lrow) * 2064);
    const uint32_t wlBase = smB + (uint32_t)(SW_WL * 4) + (uint32_t)((wn * 16 + lrow) * 2064);

    // cp.async roles: threads 0-255 load wg0's K-half, 256-511 wg1's
    const int wgL = tid >> 8;
    const int u8  = tid & 255;
    const int gbase = wgL * 8;                  // flag group base for this loader half
    uint32_t dH[2], dL[2];
#pragma unroll
    for (int b = 0; b < 2; b++) {
        dH[b] = smB + (uint32_t)((SW_A + ((wgL * 2 + b) * 2 + 0) * A_ARR) * 4);
        dL[b] = smB + (uint32_t)((SW_A + ((wgL * 2 + b) * 2 + 1) * A_ARR) * 4);
    }

    // epilogue map + register cell state (threads 0-255)
    const int eb  = tid >> 2;
    const int ejj = (tid & 3) * 2;
    float2 cv = make_float2(0.0f, 0.0f);
    const float* xgp_base = &xg[(size_t)((tid < 256 ? eb : 0) * Tm) * G4 + h0 + ejj];

    float2 xgp[4];
    if (tid < 256) {
#pragma unroll
        for (int gt = 0; gt < 4; gt++)
            xgp[gt] = __ldg((const float2*)(xgp_base + gt * Hm));
    }

    __syncthreads();   // W smem ready

    for (int t = 0; t < Tm; t++) {
        const unsigned need = 8u * (unsigned)t;   // 8 producers x t publishes
        const uint32_t* hinH  = hbH + (t & 1) * HBUF;
        const uint32_t* hinL  = hbL + (t & 1) * HBUF;
        uint32_t*       houtH = hbH + ((t + 1) & 1) * HBUF;
        uint32_t*       houtL = hbL + ((t + 1) & 1) * HBUF;

        auto wait_grp = [&](int kc) {
            if (need == 0) return;
            const unsigned* f = &flags[gbase + kc];
            while (ld_acq(f) < need) { }
        };

        auto issue_chunk = [&](int kc, int buf) {
#pragma unroll
            for (int i = 0; i < 2; i++) {
                const int u = u8 + 256 * i;
                const int r = u >> 3, cu = (u & 7) * 4;
                const int gi = r * K2 + wgL * 256 + kc * 32 + cu;
                const uint32_t ds = (uint32_t)((r * 36 + cu) * 4);
                cpasync16(dH[buf] + ds, hinH + gi);
                cpasync16(dL[buf] + ds, hinL + gi);
            }
            asm volatile("cp.async.commit_group;" ::: "memory");
        };

        float acc[2][4];
#pragma unroll
        for (int p = 0; p < 2; p++)
#pragma unroll
            for (int q = 0; q < 4; q++) acc[p][q] = 0.0f;

        wait_grp(0);
        issue_chunk(0, 0);
#pragma unroll 1
        for (int kc = 0; kc < 8; kc++) {
            if (kc + 1 < 8) wait_grp(kc + 1);    // overlap wait with in-flight load
            asm volatile("cp.async.wait_group 0;" ::: "memory");
            __syncthreads();
            if (kc + 1 < 8) issue_chunk(kc + 1, (kc + 1) & 1);

            const uint32_t aB_ = aHiB[kc & 1], alB_ = aLoB[kc & 1];
#pragma unroll
            for (int k16 = 0; k16 < 4; k16++) {
                const uint32_t acoff = (uint32_t)((k16 * 2 + lhalf) * 16);
                const uint32_t wcoff = (uint32_t)(((wg * 32 + kc * 4 + k16) * 2 + lhalf) * 16);
                uint32_t ah0, ah1, ah2, ah3, al0, al1, al2, al3;
                uint32_t bh0, bh1, bh2, bh3, bl0, bl1, bl2, bl3;
                ldsm4(ah0, ah1, ah2, ah3, aB_  + acoff);
                ldsm4(al0, al1, al2, al3, alB_ + acoff);
                ldsm4(bh0, bh1, bh2, bh3, wBase  + wcoff);
                ldsm4(bl0, bl1, bl2, bl3, wlBase + wcoff);
                mma_bf16(acc[0], ah0, ah1, ah2, ah3, bh0, bh2);
                mma_bf16(acc[1], ah0, ah1, ah2, ah3, bh1, bh3);
                mma_bf16(acc[0], ah0, ah1, ah2, ah3, bl0, bl2);
                mma_bf16(acc[1], ah0, ah1, ah2, ah3, bl1, bl3);
                mma_bf16(acc[0], al0, al1, al2, al3, bh0, bh2);
                mma_bf16(acc[1], al0, al1, al2, al3, bh1, bh3);
            }
        }

        // stage partial gate sums (per warpgroup)
        {
            float* gsW = (wg == 0) ? gs0 : gs1;
            const int r0 = wm * 16 + g, r1 = r0 + 8;
#pragma unroll
            for (int p = 0; p < 2; p++) {
                const int c = wn * 16 + p * 8 + 2 * tig;
                gsW[r0 * 34 + c] = acc[p][0]; gsW[r0 * 34 + c + 1] = acc[p][1];
                gsW[r1 * 34 + c] = acc[p][2]; gsW[r1 * 34 + c + 1] = acc[p][3];
            }
        }
        __syncthreads();

        // activations + cell update (threads 0-255)
        if (tid < 256) {
            float gate[4][2];
#pragma unroll
            for (int gt = 0; gt < 4; gt++) {
                const int c0 = eb * 34 + 8 * gt + ejj;
                gate[gt][0] = gs0[c0]     + gs1[c0]     + xgp[gt].x;
                gate[gt][1] = gs0[c0 + 1] + gs1[c0 + 1] + xgp[gt].y;
            }
            float hv[2];
#pragma unroll
            for (int e = 0; e < 2; e++) {
                const float iv = sigf(gate[0][e]);
                const float fv = sigf(gate[1][e]);
                const float gv = tanhx(gate[2][e]);
                const float ov = sigf(gate[3][e]);
                const float cc = (e == 0 ? cv.x : cv.y);
                const float cn = fv * cc + iv * gv;
                if (e == 0) cv.x = cn; else cv.y = cn;
                hv[e] = ov * tanhx(cn);
            }

            const __nv_bfloat16 b0 = __float2bfloat16_rn(hv[0]);
            const __nv_bfloat16 b1 = __float2bfloat16_rn(hv[1]);
            const __nv_bfloat16 l0 = __float2bfloat16_rn(hv[0] - __bfloat162float(b0));
            const __nv_bfloat16 l1 = __float2bfloat16_rn(hv[1] - __bfloat162float(b1));
            const uint32_t uhi = (uint32_t)__bfloat16_as_ushort(b0) | ((uint32_t)__bfloat16_as_ushort(b1) << 16);
            const uint32_t ulo = (uint32_t)__bfloat16_as_ushort(l0) | ((uint32_t)__bfloat16_as_ushort(l1) << 16);
            const int hidx = (eb * Hm + h0 + ejj) >> 1;
            houtH[hidx] = uhi;
            houtL[hidx] = ulo;
            if (seqH) {
                const int si = ((eb * Tm + t) * Hm + h0 + ejj) >> 1;
                seqH[si] = uhi;
                seqL[si] = ulo;
            }
        }

        // ---- publish this CTA's h(t+1): one fence + one group atomic ----
        __syncthreads();
        if (tid == 0) {
            __threadfence();
            atomicAdd(&flags[mygrp], 1u);
        }
        // prefetch xg for t+1 while peers publish
        if (t + 1 < Tm && tid < 256) {
#pragma unroll
            for (int gt = 0; gt < 4; gt++)
                xgp[gt] = __ldg((const float2*)(xgp_base + (t + 1) * G4 + gt * Hm));
        }
        // NOTE: no grid barrier — next step's chunk waits gate progress.
    }
}

// ---------------------------------------------------------------------------
extern "C" void kernel_launch(void* const* d_in, const int* in_sizes, int n_in,
                              void* d_out, int out_size)
{
    const float* x     = (const float*)d_in[0];
    const float* W_ih0 = (const float*)d_in[1];
    const float* W_hh0 = (const float*)d_in[2];
    const float* b_ih0 = (const float*)d_in[3];
    const float* b_hh0 = (const float*)d_in[4];
    const float* W_ih1 = (const float*)d_in[5];
    const float* W_hh1 = (const float*)d_in[6];
    const float* b_ih1 = (const float*)d_in[7];
    const float* b_hh1 = (const float*)d_in[8];
    const float* fc_w  = (const float*)d_in[9];
    const float* fc_b  = (const float*)d_in[10];
    float* out = (float*)d_out;

    uint32_t *xh, *xl, *sh, *sl, *wih0h, *wih0l, *whh0h, *whh0l;
    uint32_t *wih1h, *wih1l, *whh1h, *whh1l, *fwh, *fwl;
    uint32_t *h0h, *h0l, *h1h, *h1l;
    float *xg;
    unsigned* flags;
    cudaGetSymbolAddress((void**)&xh, g_xh);       cudaGetSymbolAddress((void**)&xl, g_xl);
    cudaGetSymbolAddress((void**)&sh, g_sh);       cudaGetSymbolAddress((void**)&sl, g_sl);
    cudaGetSymbolAddress((void**)&wih0h, g_wih0h); cudaGetSymbolAddress((void**)&wih0l, g_wih0l);
    cudaGetSymbolAddress((void**)&whh0h, g_whh0h); cudaGetSymbolAddress((void**)&whh0l, g_whh0l);
    cudaGetSymbolAddress((void**)&wih1h, g_wih1h); cudaGetSymbolAddress((void**)&wih1l, g_wih1l);
    cudaGetSymbolAddress((void**)&whh1h, g_whh1h); cudaGetSymbolAddress((void**)&whh1l, g_whh1l);
    cudaGetSymbolAddress((void**)&fwh, g_fwh);     cudaGetSymbolAddress((void**)&fwl, g_fwl);
    cudaGetSymbolAddress((void**)&h0h, g_h0h);     cudaGetSymbolAddress((void**)&h0l, g_h0l);
    cudaGetSymbolAddress((void**)&h1h, g_h1h);     cudaGetSymbolAddress((void**)&h1l, g_h1l);
    cudaGetSymbolAddress((void**)&xg, g_xg);
    cudaGetSymbolAddress((void**)&flags, g_flags);

    static bool attrSet = false;
    if (!attrSet) {
        cudaFuncSetAttribute(lstm_persist, cudaFuncAttributeMaxDynamicSharedMemorySize,
                             SMEM_UINTS * 4);
        attrSet = true;
    }

    const int HBUF = Bm * Hm / 2;

    // launch order keeps ncu (-s 5 -c 1) on lstm_persist (layer 1):
    // 0 splitall, 1 zeroh, 2 gemmT, 3 lstm0, 4 gemmT, 5 lstm1, 6 gemmT(FC)
    splitall<<<(STOT + 255) / 256, 256>>>(x, W_ih0, W_hh0, W_ih1, W_hh1, fc_w,
                                          xh, xl, wih0h, wih0l, whh0h, whh0l,
                                          wih1h, wih1l, whh1h, whh1l, fwh, fwl);
    zeroh<<<(2 * HBUF + 255) / 256, 256>>>(h0h, h0l, h1h, h1l, 2 * HBUF, flags);

    gemmT<<<dim3(G4 / 128, BT / 128), 256>>>(xh, xl, wih0h, wih0l,
                                             b_ih0, b_hh0, xg, BT, G4, DIN);
    lstm_persist<<<NCTA, 512, SMEM_UINTS * 4>>>(whh0h, whh0l, h0h, h0l, xg, sh, sl,
                                                flags);

    gemmT<<<dim3(G4 / 128, BT / 128), 256>>>(sh, sl, wih1h, wih1l,
                                             b_ih1, b_hh1, xg, BT, G4, Hm);
    lstm_persist<<<NCTA, 512, SMEM_UINTS * 4>>>(whh1h, whh1l, h1h, h1l, xg,
                                                (uint32_t*)nullptr, (uint32_t*)nullptr,
                                                flags + 16);

    gemmT<<<dim3((C_OUT + 127) / 128, 1), 256>>>(h1h, h1l, fwh, fwl,
                                                 fc_b, (const float*)nullptr,
                                                 out, Bm, C_OUT, Hm);
}

// round 10
// speedup vs baseline: 1.1491x; 1.1491x over previous
#include <cuda_runtime.h>
#include <cuda_bf16.h>
#include <stdint.h>
#include <math.h>

#define Bm 64
#define Tm 256
#define DIN 512
#define Hm 1024
#define G4 4096
#define C_OUT 1000
#define BT (Bm*Tm)
#define NCTA 128

// ---------------- device scratch (packed bf16 pairs: 2 elems / uint32) ------
__device__ uint32_t g_xh[BT*DIN/2],  g_xl[BT*DIN/2];
__device__ uint32_t g_sh[(size_t)BT*Hm/2], g_sl[(size_t)BT*Hm/2];
__device__ uint32_t g_wih0h[G4*DIN/2], g_wih0l[G4*DIN/2];
__device__ uint32_t g_whh0h[G4*Hm/2],  g_whh0l[G4*Hm/2];
__device__ uint32_t g_wih1h[G4*Hm/2],  g_wih1l[G4*Hm/2];
__device__ uint32_t g_whh1h[G4*Hm/2],  g_whh1l[G4*Hm/2];
__device__ uint32_t g_fwh[C_OUT*Hm/2], g_fwl[C_OUT*Hm/2];
__device__ uint32_t g_h0h[2*Bm*Hm/2], g_h0l[2*Bm*Hm/2];
__device__ uint32_t g_h1h[2*Bm*Hm/2], g_h1l[2*Bm*Hm/2];
__device__ float    g_xg[(size_t)BT*G4];

// grid barrier state
__device__ unsigned g_cnt = 0;
__device__ volatile unsigned g_gen = 0;

// ---------------- helpers ----------------------------------------------------
__device__ __forceinline__ float sigf(float x) { return 1.0f / (1.0f + __expf(-x)); }
__device__ __forceinline__ float tanhx(float x) {
    float a = fabsf(x);
    float e = __expf(-2.0f * a);
    float r = (1.0f - e) / (1.0f + e);
    return x < 0.0f ? -r : r;
}
__device__ __forceinline__ uint32_t smemu32(const void* p) {
    return (uint32_t)__cvta_generic_to_shared(p);
}
__device__ __forceinline__ void ldsm4(uint32_t& r0, uint32_t& r1, uint32_t& r2, uint32_t& r3,
                                      uint32_t addr) {
    asm volatile("ldmatrix.sync.aligned.m8n8.x4.shared.b16 {%0,%1,%2,%3}, [%4];"
                 : "=r"(r0), "=r"(r1), "=r"(r2), "=r"(r3) : "r"(addr));
}
__device__ __forceinline__ void mma_bf16(float* c,
    uint32_t a0, uint32_t a1, uint32_t a2, uint32_t a3, uint32_t b0, uint32_t b1)
{
    asm volatile(
        "mma.sync.aligned.m16n8k16.row.col.f32.bf16.bf16.f32 "
        "{%0,%1,%2,%3}, {%4,%5,%6,%7}, {%8,%9}, {%0,%1,%2,%3};\n"
        : "+f"(c[0]), "+f"(c[1]), "+f"(c[2]), "+f"(c[3])
        : "r"(a0), "r"(a1), "r"(a2), "r"(a3), "r"(b0), "r"(b1));
}
__device__ __forceinline__ void cpasync16(uint32_t smem_dst, const void* gsrc) {
    asm volatile("cp.async.cg.shared.global [%0], [%1], 16;" :: "r"(smem_dst), "l"(gsrc));
}
#define NBAR(id, cnt) asm volatile("bar.sync %0, %1;" :: "r"(id), "r"(cnt) : "memory")

// ---------------- fused split: all 6 fp32 tensors -> bf16 hi/lo -------------
#define S0 (BT*DIN/2)
#define S1 (G4*DIN/2)
#define S2 (G4*Hm/2)
#define STOT (S0 + S1 + 3*S2 + C_OUT*Hm/2)

__global__ void splitall(
    const float* __restrict__ x,  const float* __restrict__ wi0,
    const float* __restrict__ wh0, const float* __restrict__ wi1,
    const float* __restrict__ wh1, const float* __restrict__ fw,
    uint32_t* xh, uint32_t* xl, uint32_t* wi0h, uint32_t* wi0l,
    uint32_t* wh0h, uint32_t* wh0l, uint32_t* wi1h, uint32_t* wi1l,
    uint32_t* wh1h, uint32_t* wh1l, uint32_t* fwh, uint32_t* fwl)
{
    int i = blockIdx.x * blockDim.x + threadIdx.x;
    if (i >= STOT) return;
    const float* s; uint32_t *H, *L; int off;
    if      (i < S0)                   { s = x;   H = xh;   L = xl;   off = i; }
    else if (i < S0 + S1)              { s = wi0; H = wi0h; L = wi0l; off = i - S0; }
    else if (i < S0 + S1 + S2)         { s = wh0; H = wh0h; L = wh0l; off = i - S0 - S1; }
    else if (i < S0 + S1 + 2*S2)       { s = wi1; H = wi1h; L = wi1l; off = i - S0 - S1 - S2; }
    else if (i < S0 + S1 + 3*S2)       { s = wh1; H = wh1h; L = wh1l; off = i - S0 - S1 - 2*S2; }
    else                               { s = fw;  H = fwh;  L = fwl;  off = i - S0 - S1 - 3*S2; }
    float2 v = ((const float2*)s)[off];
    __nv_bfloat16 h0 = __float2bfloat16_rn(v.x);
    __nv_bfloat16 h1 = __float2bfloat16_rn(v.y);
    __nv_bfloat16 l0 = __float2bfloat16_rn(v.x - __bfloat162float(h0));
    __nv_bfloat16 l1 = __float2bfloat16_rn(v.y - __bfloat162float(h1));
    H[off] = (uint32_t)__bfloat16_as_ushort(h0) | ((uint32_t)__bfloat16_as_ushort(h1) << 16);
    L[off] = (uint32_t)__bfloat16_as_ushort(l0) | ((uint32_t)__bfloat16_as_ushort(l1) << 16);
}

__global__ void zeroh(uint32_t* a, uint32_t* b, uint32_t* c, uint32_t* d, int n) {
    int i = blockIdx.x * blockDim.x + threadIdx.x;
    if (i < n) { a[i] = 0; b[i] = 0; c[i] = 0; d[i] = 0; }
}

// ============================================================================
// gemmT: unchanged (bf16x3, smem-staged + ldmatrix, mma.sync). Input GEMMs + FC.
// ============================================================================
__global__ __launch_bounds__(256, 1) void gemmT(
    const uint32_t* __restrict__ Ah, const uint32_t* __restrict__ Al,
    const uint32_t* __restrict__ Bh, const uint32_t* __restrict__ Bl,
    const float* __restrict__ b1, const float* __restrict__ b2,
    float* __restrict__ C, int M, int N, int K)
{
    __shared__ uint32_t AhS[128 * 20], AlS[128 * 20], BhS[128 * 20], BlS[128 * 20];

    const int K2 = K >> 1;
    const int tid = threadIdx.x;
    const int wid = tid >> 5, lane = tid & 31;
    const int g = lane >> 2, tig = lane & 3;
    const int wm = wid >> 2, wn = wid & 3;
    const int bm = blockIdx.y * 128, bn = blockIdx.x * 128;

    const int lr0 = tid >> 2, lc = tid & 3;
    const int ar0 = min(bm + lr0, M - 1) * K2;
    const int ar1 = min(bm + lr0 + 64, M - 1) * K2;
    const int br0 = ((bn + lr0      < N) ? bn + lr0      : 0) * K2;
    const int br1 = ((bn + lr0 + 64 < N) ? bn + lr0 + 64 : 0) * K2;

    uint4 pA0, pA1, pAl0, pAl1, pB0, pB1, pBl0, pBl1;
    auto loadG = [&](int kc) {
        const int go = kc * 16 + lc * 4;
        pA0  = *(const uint4*)&Ah[ar0 + go];  pA1  = *(const uint4*)&Ah[ar1 + go];
        pAl0 = *(const uint4*)&Al[ar0 + go];  pAl1 = *(const uint4*)&Al[ar1 + go];
        pB0  = *(const uint4*)&Bh[br0 + go];  pB1  = *(const uint4*)&Bh[br1 + go];
        pBl0 = *(const uint4*)&Bl[br0 + go];  pBl1 = *(const uint4*)&Bl[br1 + go];
    };

    float acc[4][4][4];
#pragma unroll
    for (int im = 0; im < 4; im++)
#pragma unroll
        for (int p = 0; p < 4; p++)
#pragma unroll
            for (int q = 0; q < 4; q++) acc[im][p][q] = 0.0f;

    const int lrow = lane & 15, lhalf = lane >> 4;
    const uint32_t aBase = smemu32(AhS), alBase = smemu32(AlS);
    const uint32_t bBase = smemu32(BhS), blBase = smemu32(BlS);

    const int nk = K >> 5;
    loadG(0);
    for (int kc = 0; kc < nk; kc++) {
        __syncthreads();
        {
            const int s0 = lr0 * 20 + lc * 4, s1 = (lr0 + 64) * 20 + lc * 4;
            *(uint4*)&AhS[s0] = pA0;  *(uint4*)&AhS[s1] = pA1;
            *(uint4*)&AlS[s0] = pAl0; *(uint4*)&AlS[s1] = pAl1;
            *(uint4*)&BhS[s0] = pB0;  *(uint4*)&BhS[s1] = pB1;
            *(uint4*)&BlS[s0] = pBl0; *(uint4*)&BlS[s1] = pBl1;
        }
        __syncthreads();
        if (kc + 1 < nk) loadG(kc + 1);

#pragma unroll
        for (int k16 = 0; k16 < 2; k16++) {
            const uint32_t coff = (uint32_t)((k16 * 2 + lhalf) * 16);
            uint32_t bh[2][4], bl[2][4];
#pragma unroll
            for (int p16 = 0; p16 < 2; p16++) {
                const uint32_t bro = (uint32_t)((wn * 32 + p16 * 16 + lrow) * 80);
                ldsm4(bh[p16][0], bh[p16][1], bh[p16][2], bh[p16][3], bBase + bro + coff);
                ldsm4(bl[p16][0], bl[p16][1], bl[p16][2], bl[p16][3], blBase + bro + coff);
            }
#pragma unroll
            for (int im = 0; im < 4; im++) {
                const uint32_t aro = (uint32_t)((wm * 64 + im * 16 + lrow) * 80);
                uint32_t ah0, ah1, ah2, ah3, al0, al1, al2, al3;
                ldsm4(ah0, ah1, ah2, ah3, aBase + aro + coff);
                ldsm4(al0, al1, al2, al3, alBase + aro + coff);
#pragma unroll
                for (int p16 = 0; p16 < 2; p16++) {
                    mma_bf16(acc[im][p16 * 2 + 0], ah0, ah1, ah2, ah3, bh[p16][0], bh[p16][2]);
                    mma_bf16(acc[im][p16 * 2 + 1], ah0, ah1, ah2, ah3, bh[p16][1], bh[p16][3]);
                    mma_bf16(acc[im][p16 * 2 + 0], ah0, ah1, ah2, ah3, bl[p16][0], bl[p16][2]);
                    mma_bf16(acc[im][p16 * 2 + 1], ah0, ah1, ah2, ah3, bl[p16][1], bl[p16][3]);
                    mma_bf16(acc[im][p16 * 2 + 0], al0, al1, al2, al3, bh[p16][0], bh[p16][2]);
                    mma_bf16(acc[im][p16 * 2 + 1], al0, al1, al2, al3, bh[p16][1], bh[p16][3]);
                }
            }
        }
    }

#pragma unroll
    for (int im = 0; im < 4; im++) {
        const int r0 = bm + wm * 64 + im * 16 + g;
        const int r1 = r0 + 8;
#pragma unroll
        for (int p = 0; p < 4; p++) {
            const int c = bn + wn * 32 + p * 8 + 2 * tig;
            if (c < N) {
                const float bb0 = b1[c]     + (b2 ? b2[c]     : 0.0f);
                const float bb1 = b1[c + 1] + (b2 ? b2[c + 1] : 0.0f);
                if (r0 < M)
                    *(float2*)&C[(size_t)r0 * N + c] =
                        make_float2(acc[im][p][0] + bb0, acc[im][p][1] + bb1);
                if (r1 < M)
                    *(float2*)&C[(size_t)r1 * N + c] =
                        make_float2(acc[im][p][2] + bb0, acc[im][p][3] + bb1);
            }
        }
    }
}

// ============================================================================
// lstm_persist: 128 CTAs x 512 thr = 16 warps = 8 K-slices x 2 n16-tiles.
// W fragments held in REGISTERS for all 256 steps (loaded once via staged
// smem + ldmatrix). h streamed per step through 4 rotating smem buffers;
// warp-pair s loads chunk s (named barrier 1+s), buffer handoff between
// pair b and pair b+4 via named barrier 9+b. Partials reduced via smem.
// smem (uints): Abuf 4 x 8704 [hi 64x68 | lo 64x68] @0 ; red 8x64x36 @34816
// W staged temporarily at offset 0 during prologue (16512 uints).
// ============================================================================
#define ABUF_U   8704
#define ALO_U    4352
#define RED_U    34816
#define SMEM_UINTS (34816 + 18432)     // 53248 uints = 212992 B

__global__ __launch_bounds__(512, 1) void lstm_persist(
    const uint32_t* __restrict__ Wg_h, const uint32_t* __restrict__ Wg_l,
    uint32_t* __restrict__ hbH, uint32_t* __restrict__ hbL,
    const float* __restrict__ xg,
    uint32_t* __restrict__ seqH, uint32_t* __restrict__ seqL)
{
    extern __shared__ uint32_t sm[];
    float* red = (float*)(sm + RED_U);

    const int tid = threadIdx.x;
    const int wid = tid >> 5, lane = tid & 31;
    const int g = lane >> 2, tig = lane & 3;
    const int s  = wid >> 1;              // K-slice 0..7 (128 K-elems each)
    const int nn = wid & 1;               // n16 tile 0..1
    const int h0 = blockIdx.x * 8;
    const int K2 = Hm / 2;
    const int HBUF = Bm * Hm / 2;
    const int lrow = lane & 15, lhalf = lane >> 4;
    const uint32_t smB = smemu32(sm);

    // ---- prologue: W fragments -> registers (stage hi, extract; stage lo) --
    uint32_t whi[8][4], wlo[8][4];
    {
        // stage Whi at smem offset 0 (32 rows x 516 uints)
        for (int i = tid; i < 4128; i += 512) {
            const int r = i >> 7, c4 = i & 127;
            const int grow = ((r >> 3) * Hm + h0 + (r & 7)) * K2;
            *(uint4*)&sm[r * 516 + c4 * 4] = *(const uint4*)&Wg_h[grow + c4 * 4];
        }
        __syncthreads();
        const uint32_t wrowB = smB + (uint32_t)((nn * 16 + lrow) * 2064);
#pragma unroll
        for (int k16 = 0; k16 < 8; k16++) {
            const uint32_t off = (uint32_t)(((s * 8 + k16) * 2 + lhalf) * 16);
            ldsm4(whi[k16][0], whi[k16][1], whi[k16][2], whi[k16][3], wrowB + off);
        }
        __syncthreads();
        for (int i = tid; i < 4128; i += 512) {
            const int r = i >> 7, c4 = i & 127;
            const int grow = ((r >> 3) * Hm + h0 + (r & 7)) * K2;
            *(uint4*)&sm[r * 516 + c4 * 4] = *(const uint4*)&Wg_l[grow + c4 * 4];
        }
        __syncthreads();
#pragma unroll
        for (int k16 = 0; k16 < 8; k16++) {
            const uint32_t off = (uint32_t)(((s * 8 + k16) * 2 + lhalf) * 16);
            ldsm4(wlo[k16][0], wlo[k16][1], wlo[k16][2], wlo[k16][3], wrowB + off);
        }
        __syncthreads();
    }

    // epilogue state (threads 0..255)
    const int eb  = tid >> 2;
    const int ejj = (tid & 3) * 2;
    float2 cv = make_float2(0.0f, 0.0f);
    const float* xgp_base = &xg[(size_t)((tid < 256 ? eb : 0) * Tm) * G4 + h0 + ejj];
    float2 xgp[4];
    if (tid < 256) {
#pragma unroll
        for (int gt = 0; gt < 4; gt++)
            xgp[gt] = __ldg((const float2*)(xgp_base + gt * Hm));
    }

    // pair-load map: 64 threads per pair; lane64 = tid & 63
    const int lane64 = tid & 63;
    const int bufb = s & 3;
    const uint32_t bufBase = smB + (uint32_t)(bufb * ABUF_U * 4);

    for (int t = 0; t < Tm; t++) {
        const uint32_t* hinH  = hbH + (t & 1) * HBUF;
        const uint32_t* hinL  = hbL + (t & 1) * HBUF;
        uint32_t*       houtH = hbH + ((t + 1) & 1) * HBUF;
        uint32_t*       houtL = hbL + ((t + 1) & 1) * HBUF;

        // wave 2 (s >= 4): wait for buffer handoff from pair s-4
        if (s >= 4) NBAR(9 + bufb, 128);

        // ---- pair loads its chunk: 64 rows x 64 uints (hi + lo) ----
        {
#pragma unroll
            for (int i = 0; i < 16; i++) {
                const int u = lane64 + 64 * i;           // 1024 uint4 units
                const int r = u >> 4, cu = (u & 15) * 4;
                const uint32_t ds = bufBase + (uint32_t)((r * 68 + cu) * 4);
                const int src = r * K2 + s * 64 + cu;
                cpasync16(ds, hinH + src);
                cpasync16(ds + ALO_U * 4, hinL + src);
            }
            asm volatile("cp.async.commit_group;" ::: "memory");
            asm volatile("cp.async.wait_group 0;" ::: "memory");
            NBAR(1 + s, 64);                             // pair's loads visible
        }

        // ---- compute: 8 k16, A ldsm + mma with register-resident W ----
        float acc[4][2][4];
#pragma unroll
        for (int im = 0; im < 4; im++)
#pragma unroll
            for (int p = 0; p < 2; p++)
#pragma unroll
                for (int q = 0; q < 4; q++) acc[im][p][q] = 0.0f;

#pragma unroll
        for (int k16 = 0; k16 < 8; k16++) {
            const uint32_t coff = (uint32_t)((k16 * 2 + lhalf) * 16);
#pragma unroll
            for (int im = 0; im < 4; im++) {
                const uint32_t aro = bufBase + (uint32_t)((im * 16 + lrow) * 272) + coff;
                uint32_t ah0, ah1, ah2, ah3, al0, al1, al2, al3;
                ldsm4(ah0, ah1, ah2, ah3, aro);
                ldsm4(al0, al1, al2, al3, aro + ALO_U * 4);
                mma_bf16(acc[im][0], ah0, ah1, ah2, ah3, whi[k16][0], whi[k16][2]);
                mma_bf16(acc[im][1], ah0, ah1, ah2, ah3, whi[k16][1], whi[k16][3]);
                mma_bf16(acc[im][0], ah0, ah1, ah2, ah3, wlo[k16][0], wlo[k16][2]);
                mma_bf16(acc[im][1], ah0, ah1, ah2, ah3, wlo[k16][1], wlo[k16][3]);
                mma_bf16(acc[im][0], al0, al1, al2, al3, whi[k16][0], whi[k16][2]);
                mma_bf16(acc[im][1], al0, al1, al2, al3, whi[k16][1], whi[k16][3]);
            }
        }

        // wave 1 (s < 4): hand buffer to pair s+4
        if (s < 4) NBAR(9 + bufb, 128);

        // ---- write partials: red[s][row][col] ----
        {
            float* rs = red + s * (64 * 36);
#pragma unroll
            for (int im = 0; im < 4; im++) {
                const int r0 = im * 16 + g, r1 = r0 + 8;
#pragma unroll
                for (int p = 0; p < 2; p++) {
                    const int c = nn * 16 + p * 8 + 2 * tig;
                    *(float2*)&rs[r0 * 36 + c] = make_float2(acc[im][p][0], acc[im][p][1]);
                    *(float2*)&rs[r1 * 36 + c] = make_float2(acc[im][p][2], acc[im][p][3]);
                }
            }
        }
        __syncthreads();

        // ---- epilogue: threads 0..255 sum 8 slices, activations, cell ----
        if (tid < 256) {
            float gate[4][2];
#pragma unroll
            for (int gt = 0; gt < 4; gt++) {
                const int c = gt * 8 + ejj;
                float sx = 0.0f, sy = 0.0f;
#pragma unroll
                for (int ss = 0; ss < 8; ss++) {
                    const float2 v = *(const float2*)&red[ss * (64 * 36) + eb * 36 + c];
                    sx += v.x; sy += v.y;
                }
                gate[gt][0] = sx + xgp[gt].x;
                gate[gt][1] = sy + xgp[gt].y;
            }
            float hv[2];
#pragma unroll
            for (int e = 0; e < 2; e++) {
                const float iv = sigf(gate[0][e]);
                const float fv = sigf(gate[1][e]);
                const float gv = tanhx(gate[2][e]);
                const float ov = sigf(gate[3][e]);
                const float cc = (e == 0 ? cv.x : cv.y);
                const float cn = fv * cc + iv * gv;
                if (e == 0) cv.x = cn; else cv.y = cn;
                hv[e] = ov * tanhx(cn);
            }
            const __nv_bfloat16 b0 = __float2bfloat16_rn(hv[0]);
            const __nv_bfloat16 b1 = __float2bfloat16_rn(hv[1]);
            const __nv_bfloat16 l0 = __float2bfloat16_rn(hv[0] - __bfloat162float(b0));
            const __nv_bfloat16 l1 = __float2bfloat16_rn(hv[1] - __bfloat162float(b1));
            const uint32_t uhi = (uint32_t)__bfloat16_as_ushort(b0) |
                                 ((uint32_t)__bfloat16_as_ushort(b1) << 16);
            const uint32_t ulo = (uint32_t)__bfloat16_as_ushort(l0) |
                                 ((uint32_t)__bfloat16_as_ushort(l1) << 16);
            const int hidx = (eb * Hm + h0 + ejj) >> 1;
            houtH[hidx] = uhi;
            houtL[hidx] = ulo;
            if (seqH) {
                const int si = ((eb * Tm + t) * Hm + h0 + ejj) >> 1;
                seqH[si] = uhi;
                seqL[si] = ulo;
            }
            if (t + 1 < Tm) {
#pragma unroll
                for (int gt = 0; gt < 4; gt++)
                    xgp[gt] = __ldg((const float2*)(xgp_base + (size_t)(t + 1) * G4 + gt * Hm));
            }
        }

        // ---- grid barrier (R5 nanosleep pattern) ----
        __syncthreads();
        if (tid == 0) {
            __threadfence();
            const unsigned gg = g_gen;
            if (atomicAdd(&g_cnt, 1u) == NCTA - 1) {
                g_cnt = 0;
                __threadfence();
                g_gen = gg + 1;
            } else {
                while (g_gen == gg) { __nanosleep(64); }
            }
            __threadfence();
        }
        __syncthreads();
    }
}

// ---------------------------------------------------------------------------
extern "C" void kernel_launch(void* const* d_in, const int* in_sizes, int n_in,
                              void* d_out, int out_size)
{
    const float* x     = (const float*)d_in[0];
    const float* W_ih0 = (const float*)d_in[1];
    const float* W_hh0 = (const float*)d_in[2];
    const float* b_ih0 = (const float*)d_in[3];
    const float* b_hh0 = (const float*)d_in[4];
    const float* W_ih1 = (const float*)d_in[5];
    const float* W_hh1 = (const float*)d_in[6];
    const float* b_ih1 = (const float*)d_in[7];
    const float* b_hh1 = (const float*)d_in[8];
    const float* fc_w  = (const float*)d_in[9];
    const float* fc_b  = (const float*)d_in[10];
    float* out = (float*)d_out;

    uint32_t *xh, *xl, *sh, *sl, *wih0h, *wih0l, *whh0h, *whh0l;
    uint32_t *wih1h, *wih1l, *whh1h, *whh1l, *fwh, *fwl;
    uint32_t *h0h, *h0l, *h1h, *h1l;
    float *xg;
    cudaGetSymbolAddress((void**)&xh, g_xh);       cudaGetSymbolAddress((void**)&xl, g_xl);
    cudaGetSymbolAddress((void**)&sh, g_sh);       cudaGetSymbolAddress((void**)&sl, g_sl);
    cudaGetSymbolAddress((void**)&wih0h, g_wih0h); cudaGetSymbolAddress((void**)&wih0l, g_wih0l);
    cudaGetSymbolAddress((void**)&whh0h, g_whh0h); cudaGetSymbolAddress((void**)&whh0l, g_whh0l);
    cudaGetSymbolAddress((void**)&wih1h, g_wih1h); cudaGetSymbolAddress((void**)&wih1l, g_wih1l);
    cudaGetSymbolAddress((void**)&whh1h, g_whh1h); cudaGetSymbolAddress((void**)&whh1l, g_whh1l);
    cudaGetSymbolAddress((void**)&fwh, g_fwh);     cudaGetSymbolAddress((void**)&fwl, g_fwl);
    cudaGetSymbolAddress((void**)&h0h, g_h0h);     cudaGetSymbolAddress((void**)&h0l, g_h0l);
    cudaGetSymbolAddress((void**)&h1h, g_h1h);     cudaGetSymbolAddress((void**)&h1l, g_h1l);
    cudaGetSymbolAddress((void**)&xg, g_xg);

    static bool attrSet = false;
    if (!attrSet) {
        cudaFuncSetAttribute(lstm_persist, cudaFuncAttributeMaxDynamicSharedMemorySize,
                             SMEM_UINTS * 4);
        attrSet = true;
    }

    const int HBUF = Bm * Hm / 2;

    // launch order keeps ncu (-s 5 -c 1) on lstm_persist (layer 1):
    // 0 splitall, 1 zeroh, 2 gemmT, 3 lstm0, 4 gemmT, 5 lstm1, 6 gemmT(FC)
    splitall<<<(STOT + 255) / 256, 256>>>(x, W_ih0, W_hh0, W_ih1, W_hh1, fc_w,
                                          xh, xl, wih0h, wih0l, whh0h, whh0l,
                                          wih1h, wih1l, whh1h, whh1l, fwh, fwl);
    zeroh<<<(2 * HBUF + 255) / 256, 256>>>(h0h, h0l, h1h, h1l, 2 * HBUF);

    gemmT<<<dim3(G4 / 128, BT / 128), 256>>>(xh, xl, wih0h, wih0l,
                                             b_ih0, b_hh0, xg, BT, G4, DIN);
    lstm_persist<<<NCTA, 512, SMEM_UINTS * 4>>>(whh0h, whh0l, h0h, h0l, xg, sh, sl);

    gemmT<<<dim3(G4 / 128, BT / 128), 256>>>(sh, sl, wih1h, wih1l,
                                             b_ih1, b_hh1, xg, BT, G4, Hm);
    lstm_persist<<<NCTA, 512, SMEM_UINTS * 4>>>(whh1h, whh1l, h1h, h1l, xg,
                                                (uint32_t*)nullptr, (uint32_t*)nullptr);

    gemmT<<<dim3((C_OUT + 127) / 128, 1), 256>>>(h1h, h1l, fwh, fwl,
                                                 fc_b, (const float*)nullptr,
                                                 out, Bm, C_OUT, Hm);
}

// round 11
// speedup vs baseline: 1.1929x; 1.0381x over previous
#include <cuda_runtime.h>
#include <cuda_bf16.h>
#include <stdint.h>
#include <math.h>

#define Bm 64
#define Tm 256
#define DIN 512
#define Hm 1024
#define G4 4096
#define C_OUT 1000
#define BT (Bm*Tm)
#define NCTA 128

// ---------------- device scratch (packed bf16 pairs: 2 elems / uint32) ------
__device__ uint32_t g_xh[BT*DIN/2],  g_xl[BT*DIN/2];
__device__ uint32_t g_sh[(size_t)BT*Hm/2], g_sl[(size_t)BT*Hm/2];
__device__ uint32_t g_wih0h[G4*DIN/2], g_wih0l[G4*DIN/2];
__device__ uint32_t g_whh0h[G4*Hm/2],  g_whh0l[G4*Hm/2];
__device__ uint32_t g_wih1h[G4*Hm/2],  g_wih1l[G4*Hm/2];
__device__ uint32_t g_whh1h[G4*Hm/2],  g_whh1l[G4*Hm/2];
__device__ uint32_t g_fwh[C_OUT*Hm/2], g_fwl[C_OUT*Hm/2];
__device__ uint32_t g_h0h[2*Bm*Hm/2], g_h0l[2*Bm*Hm/2];
__device__ uint32_t g_h1h[2*Bm*Hm/2], g_h1l[2*Bm*Hm/2];
__device__ float    g_xg[(size_t)BT*G4];
__device__ unsigned g_flagA[NCTA*64];   // per-CTA step flags, 256B stride
__device__ unsigned g_flagB[NCTA*64];

// ---------------- helpers ----------------------------------------------------
__device__ __forceinline__ float sigf(float x) { return 1.0f / (1.0f + __expf(-x)); }
__device__ __forceinline__ float tanhx(float x) {
    float a = fabsf(x);
    float e = __expf(-2.0f * a);
    float r = (1.0f - e) / (1.0f + e);
    return x < 0.0f ? -r : r;
}
__device__ __forceinline__ uint32_t smemu32(const void* p) {
    return (uint32_t)__cvta_generic_to_shared(p);
}
__device__ __forceinline__ void ldsm4(uint32_t& r0, uint32_t& r1, uint32_t& r2, uint32_t& r3,
                                      uint32_t addr) {
    asm volatile("ldmatrix.sync.aligned.m8n8.x4.shared.b16 {%0,%1,%2,%3}, [%4];"
                 : "=r"(r0), "=r"(r1), "=r"(r2), "=r"(r3) : "r"(addr));
}
__device__ __forceinline__ void mma_bf16(float* c,
    uint32_t a0, uint32_t a1, uint32_t a2, uint32_t a3, uint32_t b0, uint32_t b1)
{
    asm volatile(
        "mma.sync.aligned.m16n8k16.row.col.f32.bf16.bf16.f32 "
        "{%0,%1,%2,%3}, {%4,%5,%6,%7}, {%8,%9}, {%0,%1,%2,%3};\n"
        : "+f"(c[0]), "+f"(c[1]), "+f"(c[2]), "+f"(c[3])
        : "r"(a0), "r"(a1), "r"(a2), "r"(a3), "r"(b0), "r"(b1));
}
__device__ __forceinline__ void cpasync16(uint32_t smem_dst, const void* gsrc) {
    asm volatile("cp.async.cg.shared.global [%0], [%1], 16;" :: "r"(smem_dst), "l"(gsrc));
}
__device__ __forceinline__ unsigned ld_acq(const unsigned* p) {
    unsigned v;
    asm volatile("ld.acquire.gpu.global.u32 %0, [%1];" : "=r"(v) : "l"(p));
    return v;
}
__device__ __forceinline__ void st_rel(unsigned* p, unsigned v) {
    asm volatile("st.release.gpu.global.u32 [%0], %1;" :: "l"(p), "r"(v) : "memory");
}
#define NBAR(id, cnt) asm volatile("bar.sync %0, %1;" :: "r"(id), "r"(cnt) : "memory")

// ---------------- fused split: all 6 fp32 tensors -> bf16 hi/lo -------------
#define S0 (BT*DIN/2)
#define S1 (G4*DIN/2)
#define S2 (G4*Hm/2)
#define STOT (S0 + S1 + 3*S2 + C_OUT*Hm/2)

__global__ void splitall(
    const float* __restrict__ x,  const float* __restrict__ wi0,
    const float* __restrict__ wh0, const float* __restrict__ wi1,
    const float* __restrict__ wh1, const float* __restrict__ fw,
    uint32_t* xh, uint32_t* xl, uint32_t* wi0h, uint32_t* wi0l,
    uint32_t* wh0h, uint32_t* wh0l, uint32_t* wi1h, uint32_t* wi1l,
    uint32_t* wh1h, uint32_t* wh1l, uint32_t* fwh, uint32_t* fwl)
{
    int i = blockIdx.x * blockDim.x + threadIdx.x;
    if (i >= STOT) return;
    const float* s; uint32_t *H, *L; int off;
    if      (i < S0)                   { s = x;   H = xh;   L = xl;   off = i; }
    else if (i < S0 + S1)              { s = wi0; H = wi0h; L = wi0l; off = i - S0; }
    else if (i < S0 + S1 + S2)         { s = wh0; H = wh0h; L = wh0l; off = i - S0 - S1; }
    else if (i < S0 + S1 + 2*S2)       { s = wi1; H = wi1h; L = wi1l; off = i - S0 - S1 - S2; }
    else if (i < S0 + S1 + 3*S2)       { s = wh1; H = wh1h; L = wh1l; off = i - S0 - S1 - 2*S2; }
    else                               { s = fw;  H = fwh;  L = fwl;  off = i - S0 - S1 - 3*S2; }
    float2 v = ((const float2*)s)[off];
    __nv_bfloat16 h0 = __float2bfloat16_rn(v.x);
    __nv_bfloat16 h1 = __float2bfloat16_rn(v.y);
    __nv_bfloat16 l0 = __float2bfloat16_rn(v.x - __bfloat162float(h0));
    __nv_bfloat16 l1 = __float2bfloat16_rn(v.y - __bfloat162float(h1));
    H[off] = (uint32_t)__bfloat16_as_ushort(h0) | ((uint32_t)__bfloat16_as_ushort(h1) << 16);
    L[off] = (uint32_t)__bfloat16_as_ushort(l0) | ((uint32_t)__bfloat16_as_ushort(l1) << 16);
}

__global__ void zeroh(uint32_t* a, uint32_t* b, uint32_t* c, uint32_t* d, int n,
                      unsigned* fA, unsigned* fB) {
    int i = blockIdx.x * blockDim.x + threadIdx.x;
    if (i < n) { a[i] = 0; b[i] = 0; c[i] = 0; d[i] = 0; }
    if (i < NCTA * 64) { fA[i] = 0; fB[i] = 0; }
}

// ============================================================================
// gemmT: unchanged (bf16x3, smem-staged + ldmatrix, mma.sync). Input GEMMs + FC.
// ============================================================================
__global__ __launch_bounds__(256, 1) void gemmT(
    const uint32_t* __restrict__ Ah, const uint32_t* __restrict__ Al,
    const uint32_t* __restrict__ Bh, const uint32_t* __restrict__ Bl,
    const float* __restrict__ b1, const float* __restrict__ b2,
    float* __restrict__ C, int M, int N, int K)
{
    __shared__ uint32_t AhS[128 * 20], AlS[128 * 20], BhS[128 * 20], BlS[128 * 20];

    const int K2 = K >> 1;
    const int tid = threadIdx.x;
    const int wid = tid >> 5, lane = tid & 31;
    const int g = lane >> 2, tig = lane & 3;
    const int wm = wid >> 2, wn = wid & 3;
    const int bm = blockIdx.y * 128, bn = blockIdx.x * 128;

    const int lr0 = tid >> 2, lc = tid & 3;
    const int ar0 = min(bm + lr0, M - 1) * K2;
    const int ar1 = min(bm + lr0 + 64, M - 1) * K2;
    const int br0 = ((bn + lr0      < N) ? bn + lr0      : 0) * K2;
    const int br1 = ((bn + lr0 + 64 < N) ? bn + lr0 + 64 : 0) * K2;

    uint4 pA0, pA1, pAl0, pAl1, pB0, pB1, pBl0, pBl1;
    auto loadG = [&](int kc) {
        const int go = kc * 16 + lc * 4;
        pA0  = *(const uint4*)&Ah[ar0 + go];  pA1  = *(const uint4*)&Ah[ar1 + go];
        pAl0 = *(const uint4*)&Al[ar0 + go];  pAl1 = *(const uint4*)&Al[ar1 + go];
        pB0  = *(const uint4*)&Bh[br0 + go];  pB1  = *(const uint4*)&Bh[br1 + go];
        pBl0 = *(const uint4*)&Bl[br0 + go];  pBl1 = *(const uint4*)&Bl[br1 + go];
    };

    float acc[4][4][4];
#pragma unroll
    for (int im = 0; im < 4; im++)
#pragma unroll
        for (int p = 0; p < 4; p++)
#pragma unroll
            for (int q = 0; q < 4; q++) acc[im][p][q] = 0.0f;

    const int lrow = lane & 15, lhalf = lane >> 4;
    const uint32_t aBase = smemu32(AhS), alBase = smemu32(AlS);
    const uint32_t bBase = smemu32(BhS), blBase = smemu32(BlS);

    const int nk = K >> 5;
    loadG(0);
    for (int kc = 0; kc < nk; kc++) {
        __syncthreads();
        {
            const int s0 = lr0 * 20 + lc * 4, s1 = (lr0 + 64) * 20 + lc * 4;
            *(uint4*)&AhS[s0] = pA0;  *(uint4*)&AhS[s1] = pA1;
            *(uint4*)&AlS[s0] = pAl0; *(uint4*)&AlS[s1] = pAl1;
            *(uint4*)&BhS[s0] = pB0;  *(uint4*)&BhS[s1] = pB1;
            *(uint4*)&BlS[s0] = pBl0; *(uint4*)&BlS[s1] = pBl1;
        }
        __syncthreads();
        if (kc + 1 < nk) loadG(kc + 1);

#pragma unroll
        for (int k16 = 0; k16 < 2; k16++) {
            const uint32_t coff = (uint32_t)((k16 * 2 + lhalf) * 16);
            uint32_t bh[2][4], bl[2][4];
#pragma unroll
            for (int p16 = 0; p16 < 2; p16++) {
                const uint32_t bro = (uint32_t)((wn * 32 + p16 * 16 + lrow) * 80);
                ldsm4(bh[p16][0], bh[p16][1], bh[p16][2], bh[p16][3], bBase + bro + coff);
                ldsm4(bl[p16][0], bl[p16][1], bl[p16][2], bl[p16][3], blBase + bro + coff);
            }
#pragma unroll
            for (int im = 0; im < 4; im++) {
                const uint32_t aro = (uint32_t)((wm * 64 + im * 16 + lrow) * 80);
                uint32_t ah0, ah1, ah2, ah3, al0, al1, al2, al3;
                ldsm4(ah0, ah1, ah2, ah3, aBase + aro + coff);
                ldsm4(al0, al1, al2, al3, alBase + aro + coff);
#pragma unroll
                for (int p16 = 0; p16 < 2; p16++) {
                    mma_bf16(acc[im][p16 * 2 + 0], ah0, ah1, ah2, ah3, bh[p16][0], bh[p16][2]);
                    mma_bf16(acc[im][p16 * 2 + 1], ah0, ah1, ah2, ah3, bh[p16][1], bh[p16][3]);
                    mma_bf16(acc[im][p16 * 2 + 0], ah0, ah1, ah2, ah3, bl[p16][0], bl[p16][2]);
                    mma_bf16(acc[im][p16 * 2 + 1], ah0, ah1, ah2, ah3, bl[p16][1], bl[p16][3]);
                    mma_bf16(acc[im][p16 * 2 + 0], al0, al1, al2, al3, bh[p16][0], bh[p16][2]);
                    mma_bf16(acc[im][p16 * 2 + 1], al0, al1, al2, al3, bh[p16][1], bh[p16][3]);
                }
            }
        }
    }

#pragma unroll
    for (int im = 0; im < 4; im++) {
        const int r0 = bm + wm * 64 + im * 16 + g;
        const int r1 = r0 + 8;
#pragma unroll
        for (int p = 0; p < 4; p++) {
            const int c = bn + wn * 32 + p * 8 + 2 * tig;
            if (c < N) {
                const float bb0 = b1[c]     + (b2 ? b2[c]     : 0.0f);
                const float bb1 = b1[c + 1] + (b2 ? b2[c + 1] : 0.0f);
                if (r0 < M)
                    *(float2*)&C[(size_t)r0 * N + c] =
                        make_float2(acc[im][p][0] + bb0, acc[im][p][1] + bb1);
                if (r1 < M)
                    *(float2*)&C[(size_t)r1 * N + c] =
                        make_float2(acc[im][p][2] + bb0, acc[im][p][3] + bb1);
            }
        }
    }
}

// ============================================================================
// lstm_persist: 128 CTAs x 512 thr = 8 warp-pairs (K-slices) x 2 n16 warps.
// W fragments in registers (R10). NEW:
//  - two-phase hi/lo streaming: each pair owns 2 private half-buffers and
//    pipelines loads against compute with pair-local named barriers only.
//  - atomic-free flag barrier: 1 release-store per CTA into its own slot,
//    warp 0 polls all 128 flags with ballot.
// smem: pair buffers 8 x 18432B @0 ; red 8x64x36 floats @147456B
// ============================================================================
#define HALF_B   9216
#define PAIR_B   18432
#define RED_U    36864
#define SMEM_UINTS 55296     // 221184 bytes

__global__ __launch_bounds__(512, 1) void lstm_persist(
    const uint32_t* __restrict__ Wg_h, const uint32_t* __restrict__ Wg_l,
    uint32_t* __restrict__ hbH, uint32_t* __restrict__ hbL,
    const float* __restrict__ xg,
    uint32_t* __restrict__ seqH, uint32_t* __restrict__ seqL,
    unsigned* __restrict__ flags)
{
    extern __shared__ uint32_t sm[];
    float* red = (float*)(sm + RED_U);

    const int tid = threadIdx.x;
    const int wid = tid >> 5, lane = tid & 31;
    const int g = lane >> 2, tig = lane & 3;
    const int s  = wid >> 1;              // K-slice 0..7 (128 K-elems)
    const int nn = wid & 1;               // n16 tile
    const int h0 = blockIdx.x * 8;
    const int K2 = Hm / 2;
    const int HBUF = Bm * Hm / 2;
    const int lrow = lane & 15, lhalf = lane >> 4;
    const uint32_t smB = smemu32(sm);
    const int lane64 = tid & 63;
    const uint32_t pairBase = smB + (uint32_t)(s * PAIR_B);

    // ---- prologue: W fragments -> registers (stage hi, extract; stage lo) --
    uint32_t whi[8][4], wlo[8][4];
    {
        for (int i = tid; i < 4128; i += 512) {
            const int r = i >> 7, c4 = i & 127;
            const int grow = ((r >> 3) * Hm + h0 + (r & 7)) * K2;
            *(uint4*)&sm[r * 516 + c4 * 4] = *(const uint4*)&Wg_h[grow + c4 * 4];
        }
        __syncthreads();
        const uint32_t wrowB = smB + (uint32_t)((nn * 16 + lrow) * 2064);
#pragma unroll
        for (int k16 = 0; k16 < 8; k16++) {
            const uint32_t off = (uint32_t)(((s * 8 + k16) * 2 + lhalf) * 16);
            ldsm4(whi[k16][0], whi[k16][1], whi[k16][2], whi[k16][3], wrowB + off);
        }
        __syncthreads();
        for (int i = tid; i < 4128; i += 512) {
            const int r = i >> 7, c4 = i & 127;
            const int grow = ((r >> 3) * Hm + h0 + (r & 7)) * K2;
            *(uint4*)&sm[r * 516 + c4 * 4] = *(const uint4*)&Wg_l[grow + c4 * 4];
        }
        __syncthreads();
#pragma unroll
        for (int k16 = 0; k16 < 8; k16++) {
            const uint32_t off = (uint32_t)(((s * 8 + k16) * 2 + lhalf) * 16);
            ldsm4(wlo[k16][0], wlo[k16][1], wlo[k16][2], wlo[k16][3], wrowB + off);
        }
        __syncthreads();
    }

    // epilogue state (threads 0..255)
    const int eb  = tid >> 2;
    const int ejj = (tid & 3) * 2;
    float2 cv = make_float2(0.0f, 0.0f);
    const float* xgp_base = &xg[(size_t)((tid < 256 ? eb : 0) * Tm) * G4 + h0 + ejj];
    float2 xgp[4];
    if (tid < 256) {
#pragma unroll
        for (int gt = 0; gt < 4; gt++)
            xgp[gt] = __ldg((const float2*)(xgp_base + gt * Hm));
    }

    for (int t = 0; t < Tm; t++) {
        // ---- entry: wait for all CTAs to have published h(t) ----
        if (t > 0 && wid == 0) {
            const unsigned tgt = (unsigned)t;
            for (;;) {
                unsigned ok = 1;
#pragma unroll
                for (int j = 0; j < 4; j++)
                    ok &= (ld_acq(&flags[(lane * 4 + j) << 6]) >= tgt) ? 1u : 0u;
                if (__all_sync(0xFFFFFFFFu, ok)) break;
            }
        }
        __syncthreads();

        const uint32_t* hinH  = hbH + (t & 1) * HBUF;
        const uint32_t* hinL  = hbL + (t & 1) * HBUF;
        uint32_t*       houtH = hbH + ((t + 1) & 1) * HBUF;
        uint32_t*       houtL = hbL + ((t + 1) & 1) * HBUF;

        auto issue_half = [&](const uint32_t* src, int half, int buf) {
            const uint32_t dst = pairBase + (uint32_t)(buf * HALF_B);
#pragma unroll
            for (int i = 0; i < 8; i++) {
                const int u = lane64 + 64 * i;       // 512 uint4 units
                const int r = u >> 3, cu = (u & 7) * 4;
                cpasync16(dst + (uint32_t)((r * 36 + cu) * 4),
                          src + r * K2 + s * 64 + half * 32 + cu);
            }
            asm volatile("cp.async.commit_group;" ::: "memory");
        };

        float acc[4][2][4];
#pragma unroll
        for (int im = 0; im < 4; im++)
#pragma unroll
            for (int p = 0; p < 2; p++)
#pragma unroll
                for (int q = 0; q < 4; q++) acc[im][p][q] = 0.0f;

        auto comp_hi = [&](int buf, int kkb) {
            const uint32_t base = pairBase + (uint32_t)(buf * HALF_B);
#pragma unroll
            for (int k = 0; k < 4; k++) {
                const uint32_t coff = (uint32_t)((k * 2 + lhalf) * 16);
                const int kk = kkb + k;
#pragma unroll
                for (int im = 0; im < 4; im++) {
                    uint32_t a0, a1, a2, a3;
                    ldsm4(a0, a1, a2, a3, base + (uint32_t)((im * 16 + lrow) * 144) + coff);
                    mma_bf16(acc[im][0], a0, a1, a2, a3, whi[kk][0], whi[kk][2]);
                    mma_bf16(acc[im][1], a0, a1, a2, a3, whi[kk][1], whi[kk][3]);
                    mma_bf16(acc[im][0], a0, a1, a2, a3, wlo[kk][0], wlo[kk][2]);
                    mma_bf16(acc[im][1], a0, a1, a2, a3, wlo[kk][1], wlo[kk][3]);
                }
            }
        };
        auto comp_lo = [&](int buf, int kkb) {
            const uint32_t base = pairBase + (uint32_t)(buf * HALF_B);
#pragma unroll
            for (int k = 0; k < 4; k++) {
                const uint32_t coff = (uint32_t)((k * 2 + lhalf) * 16);
                const int kk = kkb + k;
#pragma unroll
                for (int im = 0; im < 4; im++) {
                    uint32_t a0, a1, a2, a3;
                    ldsm4(a0, a1, a2, a3, base + (uint32_t)((im * 16 + lrow) * 144) + coff);
                    mma_bf16(acc[im][0], a0, a1, a2, a3, whi[kk][0], whi[kk][2]);
                    mma_bf16(acc[im][1], a0, a1, a2, a3, whi[kk][1], whi[kk][3]);
                }
            }
        };

        // ---- pipelined streaming (pair-local only) ----
        issue_half(hinH, 0, 0);                                    // G1
        issue_half(hinH, 1, 1);                                    // G2
        asm volatile("cp.async.wait_group 1;" ::: "memory");       // G1 done
        NBAR(1 + s, 64);
        comp_hi(0, 0);
        NBAR(1 + s, 64);                                           // buf0 free
        issue_half(hinL, 0, 0);                                    // G3
        asm volatile("cp.async.wait_group 1;" ::: "memory");       // G2 done
        NBAR(1 + s, 64);
        comp_hi(1, 4);
        NBAR(1 + s, 64);                                           // buf1 free
        issue_half(hinL, 1, 1);                                    // G4
        asm volatile("cp.async.wait_group 1;" ::: "memory");       // G3 done
        NBAR(1 + s, 64);
        comp_lo(0, 0);
        asm volatile("cp.async.wait_group 0;" ::: "memory");       // G4 done
        NBAR(1 + s, 64);
        comp_lo(1, 4);

        // ---- write partials ----
        {
            float* rs = red + s * (64 * 36);
#pragma unroll
            for (int im = 0; im < 4; im++) {
                const int r0 = im * 16 + g, r1 = r0 + 8;
#pragma unroll
                for (int p = 0; p < 2; p++) {
                    const int c = nn * 16 + p * 8 + 2 * tig;
                    *(float2*)&rs[r0 * 36 + c] = make_float2(acc[im][p][0], acc[im][p][1]);
                    *(float2*)&rs[r1 * 36 + c] = make_float2(acc[im][p][2], acc[im][p][3]);
                }
            }
        }
        __syncthreads();

        // ---- epilogue (threads 0..255): reduce 8 slices, activations, cell --
        if (tid < 256) {
            float gate[4][2];
#pragma unroll
            for (int gt = 0; gt < 4; gt++) {
                const int c = gt * 8 + ejj;
                float sx = 0.0f, sy = 0.0f;
#pragma unroll
                for (int ss = 0; ss < 8; ss++) {
                    const float2 v = *(const float2*)&red[ss * (64 * 36) + eb * 36 + c];
                    sx += v.x; sy += v.y;
                }
                gate[gt][0] = sx + xgp[gt].x;
                gate[gt][1] = sy + xgp[gt].y;
            }
            float hv[2];
#pragma unroll
            for (int e = 0; e < 2; e++) {
                const float iv = sigf(gate[0][e]);
                const float fv = sigf(gate[1][e]);
                const float gv = tanhx(gate[2][e]);
                const float ov = sigf(gate[3][e]);
                const float cc = (e == 0 ? cv.x : cv.y);
                const float cn = fv * cc + iv * gv;
                if (e == 0) cv.x = cn; else cv.y = cn;
                hv[e] = ov * tanhx(cn);
            }
            const __nv_bfloat16 b0 = __float2bfloat16_rn(hv[0]);
            const __nv_bfloat16 b1 = __float2bfloat16_rn(hv[1]);
            const __nv_bfloat16 l0 = __float2bfloat16_rn(hv[0] - __bfloat162float(b0));
            const __nv_bfloat16 l1 = __float2bfloat16_rn(hv[1] - __bfloat162float(b1));
            const uint32_t uhi = (uint32_t)__bfloat16_as_ushort(b0) |
                                 ((uint32_t)__bfloat16_as_ushort(b1) << 16);
            const uint32_t ulo = (uint32_t)__bfloat16_as_ushort(l0) |
                                 ((uint32_t)__bfloat16_as_ushort(l1) << 16);
            const int hidx = (eb * Hm + h0 + ejj) >> 1;
            houtH[hidx] = uhi;
            houtL[hidx] = ulo;
            if (seqH) {
                const int si = ((eb * Tm + t) * Hm + h0 + ejj) >> 1;
                seqH[si] = uhi;
                seqL[si] = ulo;
            }
        }
        __syncthreads();                      // all h(t+1) stores issued

        // ---- publish (single release store, no atomics), then prefetch ----
        if (tid == 0) {
            __threadfence();
            st_rel(&flags[blockIdx.x << 6], (unsigned)(t + 1));
        }
        if (t + 1 < Tm && tid < 256) {
#pragma unroll
            for (int gt = 0; gt < 4; gt++)
                xgp[gt] = __ldg((const float2*)(xgp_base + (size_t)(t + 1) * G4 + gt * Hm));
        }
    }
}

// ---------------------------------------------------------------------------
extern "C" void kernel_launch(void* const* d_in, const int* in_sizes, int n_in,
                              void* d_out, int out_size)
{
    const float* x     = (const float*)d_in[0];
    const float* W_ih0 = (const float*)d_in[1];
    const float* W_hh0 = (const float*)d_in[2];
    const float* b_ih0 = (const float*)d_in[3];
    const float* b_hh0 = (const float*)d_in[4];
    const float* W_ih1 = (const float*)d_in[5];
    const float* W_hh1 = (const float*)d_in[6];
    const float* b_ih1 = (const float*)d_in[7];
    const float* b_hh1 = (const float*)d_in[8];
    const float* fc_w  = (const float*)d_in[9];
    const float* fc_b  = (const float*)d_in[10];
    float* out = (float*)d_out;

    uint32_t *xh, *xl, *sh, *sl, *wih0h, *wih0l, *whh0h, *whh0l;
    uint32_t *wih1h, *wih1l, *whh1h, *whh1l, *fwh, *fwl;
    uint32_t *h0h, *h0l, *h1h, *h1l;
    float *xg;
    unsigned *fA, *fB;
    cudaGetSymbolAddress((void**)&xh, g_xh);       cudaGetSymbolAddress((void**)&xl, g_xl);
    cudaGetSymbolAddress((void**)&sh, g_sh);       cudaGetSymbolAddress((void**)&sl, g_sl);
    cudaGetSymbolAddress((void**)&wih0h, g_wih0h); cudaGetSymbolAddress((void**)&wih0l, g_wih0l);
    cudaGetSymbolAddress((void**)&whh0h, g_whh0h); cudaGetSymbolAddress((void**)&whh0l, g_whh0l);
    cudaGetSymbolAddress((void**)&wih1h, g_wih1h); cudaGetSymbolAddress((void**)&wih1l, g_wih1l);
    cudaGetSymbolAddress((void**)&whh1h, g_whh1h); cudaGetSymbolAddress((void**)&whh1l, g_whh1l);
    cudaGetSymbolAddress((void**)&fwh, g_fwh);     cudaGetSymbolAddress((void**)&fwl, g_fwl);
    cudaGetSymbolAddress((void**)&h0h, g_h0h);     cudaGetSymbolAddress((void**)&h0l, g_h0l);
    cudaGetSymbolAddress((void**)&h1h, g_h1h);     cudaGetSymbolAddress((void**)&h1l, g_h1l);
    cudaGetSymbolAddress((void**)&xg, g_xg);
    cudaGetSymbolAddress((void**)&fA, g_flagA);
    cudaGetSymbolAddress((void**)&fB, g_flagB);

    static bool attrSet = false;
    if (!attrSet) {
        cudaFuncSetAttribute(lstm_persist, cudaFuncAttributeMaxDynamicSharedMemorySize,
                             SMEM_UINTS * 4);
        attrSet = true;
    }

    const int HBUF = Bm * Hm / 2;

    // launch order keeps ncu (-s 5 -c 1) on lstm_persist (layer 1):
    // 0 splitall, 1 zeroh, 2 gemmT, 3 lstm0, 4 gemmT, 5 lstm1, 6 gemmT(FC)
    splitall<<<(STOT + 255) / 256, 256>>>(x, W_ih0, W_hh0, W_ih1, W_hh1, fc_w,
                                          xh, xl, wih0h, wih0l, whh0h, whh0l,
                                          wih1h, wih1l, whh1h, whh1l, fwh, fwl);
    zeroh<<<(2 * HBUF + 255) / 256, 256>>>(h0h, h0l, h1h, h1l, 2 * HBUF, fA, fB);

    gemmT<<<dim3(G4 / 128, BT / 128), 256>>>(xh, xl, wih0h, wih0l,
                                             b_ih0, b_hh0, xg, BT, G4, DIN);
    lstm_persist<<<NCTA, 512, SMEM_UINTS * 4>>>(whh0h, whh0l, h0h, h0l, xg, sh, sl, fA);

    gemmT<<<dim3(G4 / 128, BT / 128), 256>>>(sh, sl, wih1h, wih1l,
                                             b_ih1, b_hh1, xg, BT, G4, Hm);
    lstm_persist<<<NCTA, 512, SMEM_UINTS * 4>>>(whh1h, whh1l, h1h, h1l, xg,
                                                (uint32_t*)nullptr, (uint32_t*)nullptr, fB);

    gemmT<<<dim3((C_OUT + 127) / 128, 1), 256>>>(h1h, h1l, fwh, fwl,
                                                 fc_b, (const float*)nullptr,
                                                 out, Bm, C_OUT, Hm);
}